// round 15
// baseline (speedup 1.0000x reference)
#include <cuda_runtime.h>
#include <math.h>

#define NB  8
#define H   12
#define DH  64
#define LV  1568
#define LA  512
#define NCV 392
#define NCA 256
#define ROW 5696
#define OFF_PROBV 0
#define OFF_PROBA 1568
#define OFF_VCLS  2080
#define OFF_ACLS  2848
#define OFF_PRAV  3616
#define OFF_PRVA  5184

// ---------- scratch ----------
__device__ int   g_cidx_v[NB * NCV];
__device__ float g_w_v[NB * NCV];
__device__ int   g_cidx_a[NB * NCA];
__device__ float g_w_a[NB * NCA];
__device__ float g_invS_av[NB];
__device__ float g_invS_va[NB];
__device__ float g_probv[NB * NCV];
__device__ float g_proba[NB * NCA];
__device__ float g_posv[NB * H * NCV];    // pos partial sums (2 writers each)
__device__ float g_posa[NB * H * NCA];
__device__ int   g_cnt1[NB * H * 2];      // per-(n,h,side): 2 arrivals
__device__ int   g_cnt2[NB * 2];          // per-(n,side): H arrivals

// ---------- kernel 1: compaction (sides 0/1) + fills/zeroing (sides 2/3) ----------
// grid (NB, 4)
__global__ void kprep(const float* __restrict__ n_attn_av,
                      const float* __restrict__ n_attn_va,
                      const int* __restrict__ ids_v,
                      const int* __restrict__ ids_a,
                      float* __restrict__ out) {
    int n = blockIdx.x, side = blockIdx.y, tid = threadIdx.x;

    if (side >= 2) {
        float* row = out + (size_t)n * ROW;
        if (side == 2) {
            for (int j = tid; j < LV; j += 512) {
                row[OFF_PROBV + j] = 0.f;
                row[OFF_PRAV + j]  = n_attn_av[n * LV + j];
            }
            for (int t = tid; t < H * NCV; t += 512) g_posv[n * H * NCV + t] = 0.f;
        } else {
            for (int j = tid; j < LA; j += 512) {
                row[OFF_PROBA + j] = 0.f;
                row[OFF_PRVA + j]  = n_attn_va[n * LA + j];
            }
            for (int t = tid; t < H * NCA; t += 512) g_posa[n * H * NCA + t] = 0.f;
            if (tid < H * 2) g_cnt1[n * H * 2 + tid] = 0;
            if (tid < 2)     g_cnt2[n * 2 + tid] = 0;
        }
        return;
    }

    int lane = tid & 31, wrp = tid >> 5;
    __shared__ int   s_rank[LV];
    __shared__ int   s_wsum[16];
    __shared__ float s_red[512];

    int full = side ? LA : LV;
    int cnt  = side ? NCA : NCV;
    const int*   ids = side ? ids_a : ids_v;
    const float* na  = side ? n_attn_va : n_attn_av;

    for (int t = tid; t < full; t += 512) s_rank[ids[n * full + t]] = t;
    if (side) { if (tid < NCA) g_proba[n * NCA + tid] = 0.f; }
    else      { if (tid < NCV) g_probv[n * NCV + tid] = 0.f; }
    __syncthreads();

    int per = (full + 511) >> 9;
    int base = tid * per;
    int keep[4]; int k = 0; float ws = 0.f;
    for (int i = 0; i < per; i++) {
        int j = base + i;
        if (j < full && s_rank[j] < cnt) { keep[k++] = j; ws += na[n * full + j]; }
    }
    int inc = k;
    for (int d = 1; d < 32; d <<= 1) {
        int v = __shfl_up_sync(0xffffffffu, inc, d);
        if (lane >= d) inc += v;
    }
    if (lane == 31) s_wsum[wrp] = inc;
    __syncthreads();
    if (wrp == 0 && lane < 16) {
        int v = s_wsum[lane];
        for (int d = 1; d < 16; d <<= 1) {
            int u = __shfl_up_sync(0xffffu, v, d);
            if (lane >= d) v += u;
        }
        s_wsum[lane] = v;
    }
    __syncthreads();
    int off = (wrp ? s_wsum[wrp - 1] : 0) + inc - k;
    for (int i = 0; i < k; i++) {
        int j = keep[i];
        int slot = off + i;
        if (side) { g_cidx_a[n * NCA + slot] = j; g_w_a[n * NCA + slot] = na[n * LA + j]; }
        else      { g_cidx_v[n * NCV + slot] = j; g_w_v[n * NCV + slot] = na[n * LV + j]; }
    }
    s_red[tid] = ws;
    __syncthreads();
    for (int s = 256; s > 0; s >>= 1) {
        if (tid < s) s_red[tid] += s_red[tid + s];
        __syncthreads();
    }
    if (tid == 0) {
        if (side) g_invS_va[n] = 1.f / s_red[0];
        else      g_invS_av[n] = 1.f / s_red[0];
    }
}

// ---------- kernel 2: S-split main with cascaded last-block finishers ----------
// grid (H, NB, 4): z=0,1 -> v side S-chunks [0,128),[128,256)
//                  z=2,3 -> a side S-chunks [0,196),[196,392)
__global__ void __launch_bounds__(512, 2)
kmain(const float* __restrict__ pos_v_q, const float* __restrict__ pos_v_k,
      const float* __restrict__ pos_a_q, const float* __restrict__ pos_a_k,
      const float* __restrict__ M_av,    const float* __restrict__ M_va,
      const float* __restrict__ spu_a_cls, const float* __restrict__ spu_v_cls,
      const float* __restrict__ n_attn_av, const float* __restrict__ n_attn_va,
      const float* __restrict__ u_v,       const float* __restrict__ u_a,
      float* __restrict__ out) {
    int h = blockIdx.x, n = blockIdx.y, z = blockIdx.z;
    int side  = (z >= 2) ? 1 : 0;
    int chunk = side ? (z - 2) : z;
    int tid = threadIdx.x;

    __shared__ int   s_idxL[NCV];
    __shared__ float s_wL[NCV];
    __shared__ int   s_offS[196];
    __shared__ float s_wS[196];
    __shared__ float s_cls[DH];
    __shared__ float s_red[512];
    __shared__ int   s_flag, s_flag2;

    int Lcnt, Scnt, slen, sbase, Mstride, clsoff;
    const float *kten, *qten, *M, *cls;
    const int *cidxL, *cidxS;
    const float *gwL, *gwS;
    float invS_pos, invS_cls;
    float *posbuf, *prob;
    if (side == 0) {
        Lcnt = NCV; Scnt = NCA; slen = 128; sbase = chunk * 128;
        Mstride = LV; clsoff = OFF_VCLS;
        kten = pos_v_k; qten = pos_v_q; M = M_av; cls = spu_a_cls;
        cidxL = g_cidx_v; cidxS = g_cidx_a;
        gwL = g_w_v; gwS = g_w_a;
        invS_pos = g_invS_va[n]; invS_cls = g_invS_av[n];
        posbuf = g_posv + (size_t)(n * H + h) * NCV;
        prob   = g_probv + n * NCV;
    } else {
        Lcnt = NCA; Scnt = NCV; slen = 196; sbase = chunk * 196;
        Mstride = LA; clsoff = OFF_ACLS;
        kten = pos_a_k; qten = pos_a_q; M = M_va; cls = spu_v_cls;
        cidxL = g_cidx_a; cidxS = g_cidx_v;
        gwL = g_w_a; gwS = g_w_v;
        invS_pos = g_invS_av[n]; invS_cls = g_invS_va[n];
        posbuf = g_posa + (size_t)(n * H + h) * NCA;
        prob   = g_proba + n * NCA;
    }

    if (tid < Lcnt) {
        s_idxL[tid] = cidxL[n * Lcnt + tid];
        s_wL[tid]   = gwL[n * Lcnt + tid];
    }
    if (tid < slen) {
        s_offS[tid] = cidxS[n * Scnt + sbase + tid] * Mstride;
        s_wS[tid]   = gwS[n * Scnt + sbase + tid];
    }
    if (tid < DH) s_cls[tid] = cls[(n * H + h) * DH + tid];
    __syncthreads();

    const float* Mbase = M + (size_t)(n * H + h) * (size_t)LA * LV;

    // ---- pos partial over this block's S-chunk ----
    if (tid < Lcnt) {
        int il = s_idxL[tid];
        float p0 = 0.f, p1 = 0.f, p2 = 0.f, p3 = 0.f;
        for (int a = 0; a < slen; a += 4) {
            p0 = fmaf(Mbase[s_offS[a + 0] + il], s_wS[a + 0], p0);
            p1 = fmaf(Mbase[s_offS[a + 1] + il], s_wS[a + 1], p1);
            p2 = fmaf(Mbase[s_offS[a + 2] + il], s_wS[a + 2], p2);
            p3 = fmaf(Mbase[s_offS[a + 3] + il], s_wS[a + 3], p3);
        }
        atomicAdd(&posbuf[tid], (p0 + p1) + (p2 + p3));
    }

    // ---- cls (chunk 0 only): weighted sum of gathered q rows ----
    if (chunk == 0) {
        const float* qbase = qten + (size_t)(n * H + h) * (side ? LA : LV) * DH;
        int g = tid >> 6, d = tid & 63;
        float a2 = 0.f;
        for (int l = g; l < Lcnt; l += 8)
            a2 = fmaf(qbase[(size_t)s_idxL[l] * DH + d], s_wL[l], a2);
        s_red[tid] = a2;
        __syncthreads();
        if (tid < DH) {
            float t = 0.f;
            #pragma unroll
            for (int gg = 0; gg < 8; gg++) t += s_red[gg * 64 + tid];
            out[(size_t)n * ROW + clsoff + h * DH + tid] = t * invS_cls;
        }
    }

    // ---- finisher 1: second block of this (n,h,side) does spu + sigmoid ----
    __threadfence();
    __syncthreads();
    if (tid == 0) {
        int t = atomicAdd(&g_cnt1[(n * H + h) * 2 + side], 1);
        s_flag = (t == 1);
    }
    __syncthreads();

    if (s_flag) {
        if (tid == 0) __threadfence();
        __syncthreads();
        if (tid < Lcnt) {
            int il = s_idxL[tid];
            const float4* krow = (const float4*)(kten
                + (size_t)(n * H + h) * (side ? LA : LV) * DH + (size_t)il * DH);
            float spu = 0.f;
            #pragma unroll
            for (int d4 = 0; d4 < DH / 4; d4++) {
                float4 v = krow[d4];
                spu = fmaf(v.x, s_cls[4 * d4 + 0], spu);
                spu = fmaf(v.y, s_cls[4 * d4 + 1], spu);
                spu = fmaf(v.z, s_cls[4 * d4 + 2], spu);
                spu = fmaf(v.w, s_cls[4 * d4 + 3], spu);
            }
            spu *= 0.125f;
            float posv = __ldcg(&posbuf[tid]) * invS_pos;
            float sig = 1.f / (1.f + __expf(posv - spu));
            atomicAdd(&prob[tid], sig);
        }
    }

    // ---- finisher 2: 12th sig-finisher of this (n,side) scatters + prunes ----
    __threadfence();
    __syncthreads();
    if (tid == 0) {
        s_flag2 = 0;
        if (s_flag) {
            int t2 = atomicAdd(&g_cnt2[n * 2 + side], 1);
            s_flag2 = (t2 == H - 1);
        }
    }
    __syncthreads();
    if (!s_flag2) return;
    if (tid == 0) __threadfence();
    __syncthreads();

    float* row = out + (size_t)n * ROW;
    if (side == 0) {
        if (tid < NCV) {
            int pos = s_idxL[tid];
            float p = __ldcg(&g_probv[n * NCV + tid]) * (1.f / 12.f);
            row[OFF_PROBV + pos] = p;
            row[OFF_PRAV + pos]  = (u_v[n * LV + pos] < p) ? 0.f : n_attn_av[n * LV + pos];
        }
    } else {
        if (tid < NCA) {
            int pos = s_idxL[tid];
            float p = __ldcg(&g_proba[n * NCA + tid]) * (1.f / 12.f);
            row[OFF_PROBA + pos] = p;
            row[OFF_PRVA + pos]  = (u_a[n * LA + pos] < p) ? 0.f : n_attn_va[n * LA + pos];
        }
    }
}

extern "C" void kernel_launch(void* const* d_in, const int* in_sizes, int n_in,
                              void* d_out, int out_size) {
    const float* pos_v_q   = (const float*)d_in[0];
    const float* pos_v_k   = (const float*)d_in[1];
    const float* pos_a_q   = (const float*)d_in[2];
    const float* pos_a_k   = (const float*)d_in[3];
    const float* M_av      = (const float*)d_in[4];
    const float* M_va      = (const float*)d_in[5];
    const float* n_attn_av = (const float*)d_in[6];
    const float* n_attn_va = (const float*)d_in[7];
    const float* spu_a_cls = (const float*)d_in[8];
    const float* spu_v_cls = (const float*)d_in[9];
    const float* u_v       = (const float*)d_in[10];
    const float* u_a       = (const float*)d_in[11];
    const int*   ids_v     = (const int*)d_in[12];
    const int*   ids_a     = (const int*)d_in[13];
    float* out = (float*)d_out;

    kprep<<<dim3(NB, 4), 512>>>(n_attn_av, n_attn_va, ids_v, ids_a, out);
    kmain<<<dim3(H, NB, 4), 512>>>(pos_v_q, pos_v_k, pos_a_q, pos_a_k,
                                   M_av, M_va, spu_a_cls, spu_v_cls,
                                   n_attn_av, n_attn_va, u_v, u_a, out);
}